// round 11
// baseline (speedup 1.0000x reference)
#include <cuda_runtime.h>
#include <cstdint>

#define SQ 512
#define NB 64
#define NH 1024
#define NI 256
#define NG 4096
#define HSEQ ((size_t)SQ*NB*NH)

// scratch (no allocations allowed)
__device__ float    g_xg[(size_t)SQ*NB*NG];     // xg = x@Wx + bx + bh
__device__ float    g_hfrag[(size_t)SQ*NB*NH];  // h in tf32 A-fragment order
__device__ unsigned g_flags[4*SQ];              // per-(group,step) arrival counters

__device__ __forceinline__ unsigned tf32u(float x){
  unsigned u; asm("cvt.rna.tf32.f32 %0, %1;" : "=r"(u) : "f"(x)); return u;
}
__device__ __forceinline__ float tf32f(float x){ return __uint_as_float(tf32u(x)); }
__device__ __forceinline__ void mma8(float d[4], unsigned a0,unsigned a1,unsigned a2,unsigned a3,
                                     unsigned b0,unsigned b1){
  asm("mma.sync.aligned.m16n8k8.row.col.f32.tf32.tf32.f32 "
      "{%0,%1,%2,%3},{%4,%5,%6,%7},{%8,%9},{%0,%1,%2,%3};"
      : "+f"(d[0]),"+f"(d[1]),"+f"(d[2]),"+f"(d[3])
      : "r"(a0),"r"(a1),"r"(a2),"r"(a3),"r"(b0),"r"(b1));
}
__device__ __forceinline__ void mma8f(float d[4], float4 A, float b0, float b1){
  mma8(d, __float_as_uint(A.x),__float_as_uint(A.y),__float_as_uint(A.z),__float_as_uint(A.w),
       __float_as_uint(b0), __float_as_uint(b1));
}
__device__ __forceinline__ float sigf(float x){ return 1.f/(1.f+__expf(-x)); }

// ---------------------------------------------------------------------------
// Phase 1: xg[m][gate*1024+j] = x[m,:] @ Wgate[:, j] + bx + bh
// CTA tile 128(M) x 64(N), K=256 in 8 chunks of 32. 8 warps = 4(m) x 2(n).
// Block (0,0) also re-zeroes the recurrence sync flags (stream-ordered before
// lstm_rec of the same kernel_launch call -> graph-replay deterministic).
// ---------------------------------------------------------------------------
__global__ void __launch_bounds__(256) xg_gemm(
    const float* __restrict__ x,
    const float* __restrict__ Wa,const float* __restrict__ Wb,
    const float* __restrict__ Wc,const float* __restrict__ Wd,
    const float* __restrict__ xa,const float* __restrict__ xb,
    const float* __restrict__ xc,const float* __restrict__ xd,
    const float* __restrict__ ha,const float* __restrict__ hb,
    const float* __restrict__ hc,const float* __restrict__ hd)
{
  __shared__ float As[128*36];
  __shared__ float Bs[32*72];
  __shared__ float bias[64];
  const int tid=threadIdx.x, w=tid>>5, lane=tid&31;
  const int g=lane>>2, tg=lane&3, wm=w>>1, wn=w&1;
  const int mbase=blockIdx.y*128, nb=blockIdx.x*64;
  const int gate=nb>>10, colbase=nb&1023;

  if (blockIdx.x==0 && blockIdx.y==0){           // flag reset for lstm_rec
    #pragma unroll
    for(int p=0;p<8;p++) g_flags[tid+p*256]=0u;
  }

  const float* Wg = gate==0?Wa:gate==1?Wb:gate==2?Wc:Wd;
  const float* bx = gate==0?xa:gate==1?xb:gate==2?xc:xd;
  const float* bh = gate==0?ha:gate==1?hb:gate==2?hc:hd;
  if (tid<64) bias[tid]=bx[colbase+tid]+bh[colbase+tid];

  float acc[2][4][4];
  #pragma unroll
  for(int i=0;i<2;i++)
    #pragma unroll
    for(int j=0;j<4;j++)
      #pragma unroll
      for(int e=0;e<4;e++) acc[i][j][e]=0.f;

  for(int kc=0;kc<8;kc++){
    #pragma unroll
    for(int p=0;p<4;p++){
      int fid=tid+p*256, row=fid>>3, c4=(fid&7)*4;
      float4 v=*(const float4*)(x+(size_t)(mbase+row)*NI+kc*32+c4);
      v.x=tf32f(v.x); v.y=tf32f(v.y); v.z=tf32f(v.z); v.w=tf32f(v.w);
      *(float4*)(As+row*36+c4)=v;
    }
    #pragma unroll
    for(int p=0;p<2;p++){
      int fid=tid+p*256, r=fid>>4, c4=(fid&15)*4;
      float4 v=*(const float4*)(Wg+(size_t)(kc*32+r)*NH+colbase+c4);
      v.x=tf32f(v.x); v.y=tf32f(v.y); v.z=tf32f(v.z); v.w=tf32f(v.w);
      *(float4*)(Bs+r*72+c4)=v;
    }
    __syncthreads();
    #pragma unroll
    for(int kk=0;kk<4;kk++){
      unsigned a[2][4];
      #pragma unroll
      for(int mt=0;mt<2;mt++){
        int ar=wm*32+mt*16+g, k0=kk*8+tg;
        a[mt][0]=__float_as_uint(As[ar*36+k0]);
        a[mt][1]=__float_as_uint(As[(ar+8)*36+k0]);
        a[mt][2]=__float_as_uint(As[ar*36+k0+4]);
        a[mt][3]=__float_as_uint(As[(ar+8)*36+k0+4]);
      }
      #pragma unroll
      for(int nt=0;nt<4;nt++){
        int nc=wn*32+nt*8+g, k0=kk*8+tg;
        unsigned b0=__float_as_uint(Bs[k0*72+nc]);
        unsigned b1=__float_as_uint(Bs[(k0+4)*72+nc]);
        mma8(acc[0][nt],a[0][0],a[0][1],a[0][2],a[0][3],b0,b1);
        mma8(acc[1][nt],a[1][0],a[1][1],a[1][2],a[1][3],b0,b1);
      }
    }
    __syncthreads();
  }
  #pragma unroll
  for(int mt=0;mt<2;mt++){
    #pragma unroll
    for(int nt=0;nt<4;nt++){
      int row0=mbase+wm*32+mt*16+g;
      int colL=wn*32+nt*8+2*tg;
      float b0v=bias[colL], b1v=bias[colL+1];
      float* o0=g_xg+(size_t)row0*NG+nb+colL;
      *(float2*)o0               = make_float2(acc[mt][nt][0]+b0v, acc[mt][nt][1]+b1v);
      *(float2*)(o0+(size_t)8*NG)= make_float2(acc[mt][nt][2]+b0v, acc[mt][nt][3]+b1v);
    }
  }
}

// ---------------------------------------------------------------------------
// Phase 2: persistent recurrence, 128 CTAs (1/SM), 512 threads (16 warps).
// CTA c owns h-cols [8c,8c+8) = k-chunk c, and the matching 8 cols of all 4
// gates. Warp w = (mt=w>>2, kh=w&3): m-tile mt, chunks 32kh..32kh+31.
//  - h exchanged via g_hfrag (tf32 A-fragments, [t][chunk][mt][lane] float4);
//    producer writes via in-warp shuffle transpose; consumers __ldcg straight
//    into MMA operands.
//  - SYNC (warp-granular): 4 producer groups (CTAs 32G..32G+31) own flag
//    g_flags[G*SQ+t]. Each kh==0 writer warp: frag STG -> __syncwarp ->
//    lane0 red.release.gpu.add(+1)  (cumulative release covers whole warp).
//    Target count = 32 CTAs x 4 warps = 128. Consumer warp (mt,kh)
//    acquire-polls flag[kh*SQ+t-1] (all lanes, same address) and starts its
//    LDG burst immediately -- no block barrier on the consume side.
//  - ONE __syncthreads per step (kh-reduction). red is double-buffered on
//    t-parity: kh>0 warps of step t+1 write the other buffer while kh==0
//    warps may still be reading step t's (they re-converge at the next
//    barrier before parity repeats).
//  - h->out store is post-arrival (nothing cross-CTA reads out).
//  - poll uses (<128) so stale flags never hang (ncu replay safe).
// ---------------------------------------------------------------------------
__global__ void __launch_bounds__(512,1) lstm_rec(
    const float* __restrict__ Wh1,const float* __restrict__ Wh2,
    const float* __restrict__ Wh3,const float* __restrict__ Wh4,
    float* __restrict__ out)
{
  extern __shared__ float sm[];
  float* Bp  = sm;               // 32768 words (128KB): packed B frags
  float* red = sm + 32768;       // 2 x 6144 words (48KB): kh partials, parity

  const int tid=threadIdx.x, w=tid>>5, lane=tid&31;
  const int g=lane>>2, tg=lane&3, cta=blockIdx.x;
  const int mt=w>>2, kh=w&3;

  { // one-time B pack: Bp[idx], idx=(s*2+p)*128 + ln*4 + e
    const float* Whs[4]={Wh1,Wh2,Wh3,Wh4};
    for(int idx=tid; idx<32768; idx+=512){
      int e=idx&3, ln=(idx>>2)&31, p=(idx>>7)&1, s=idx>>8;
      int nt=2*p+(e>>1);
      int k=8*s+(ln&3)+4*(e&1);
      Bp[idx]=tf32f(Whs[nt][(size_t)k*NH+8*cta+(ln>>2)]);
    }
  }
  __syncthreads();

  const float4* bq = (const float4*)Bp;
  float4* red4 = (float4*)red;
  unsigned* myArr = g_flags + (cta>>5)*SQ;   // producer arrival row
  unsigned* myPol = g_flags + kh*SQ;         // consumer poll row
  float cst[4]={0,0,0,0}, hv[4]={0,0,0,0};

  #pragma unroll 1
  for(int t=0;t<SQ;t++){
    // xg loads: independent of h -> issue before any waiting
    float2 xr[8];
    if(kh==0){
      const float* xb = g_xg + ((size_t)t*NB + 16*mt + g)*NG + 8*cta + 2*tg;
      #pragma unroll
      for(int nt=0;nt<4;nt++){
        xr[nt]   = __ldcg((const float2*)(xb + nt*NH));
        xr[4+nt] = __ldcg((const float2*)(xb + (size_t)8*NG + nt*NH));
      }
    }

    float accA[4][4], accB[4][4];
    #pragma unroll
    for(int n=0;n<4;n++)
      #pragma unroll
      for(int e=0;e<4;e++){ accA[n][e]=0.f; accB[n][e]=0.f; }

    if(t>0){
      { // per-warp acquire poll on this warp's producer group (all lanes)
        const unsigned* fp = myPol + (t-1);
        unsigned v;
        do {
          asm volatile("ld.acquire.gpu.global.u32 %0, [%1];" : "=r"(v) : "l"(fp) : "memory");
        } while(v < 128u);
      }
      const float4* fb = (const float4*)(g_hfrag + (size_t)(t-1)*NB*NH);
      #pragma unroll 4
      for(int cc=0; cc<32; cc+=2){
        int c0=(kh<<5)+cc;
        float4 A0 = __ldcg(fb + (c0*128 + mt*32 + lane));
        float4 P0 = bq[(c0*2+0)*32 + lane];
        float4 Q0 = bq[(c0*2+1)*32 + lane];
        float4 A1 = __ldcg(fb + ((c0+1)*128 + mt*32 + lane));
        float4 P1 = bq[((c0+1)*2+0)*32 + lane];
        float4 Q1 = bq[((c0+1)*2+1)*32 + lane];
        mma8f(accA[0],A0,P0.x,P0.y); mma8f(accA[1],A0,P0.z,P0.w);
        mma8f(accA[2],A0,Q0.x,Q0.y); mma8f(accA[3],A0,Q0.z,Q0.w);
        mma8f(accB[0],A1,P1.x,P1.y); mma8f(accB[1],A1,P1.z,P1.w);
        mma8f(accB[2],A1,Q1.x,Q1.y); mma8f(accB[3],A1,Q1.z,Q1.w);
      }
    }
    #pragma unroll
    for(int n=0;n<4;n++)
      #pragma unroll
      for(int e=0;e<4;e++) accA[n][e]+=accB[n][e];

    float4* rb = red4 + (t&1)*1536;
    if(kh>0){                             // slabs kh=1..3 -> red (parity buf)
      #pragma unroll
      for(int n=0;n<4;n++)
        rb[(((kh-1)*4+mt)*4+n)*32+lane] =
          make_float4(accA[n][0],accA[n][1],accA[n][2],accA[n][3]);
    }
    __syncthreads();                      // the ONE barrier: red ready
    if(kh==0){
      #pragma unroll
      for(int s=0;s<3;s++)
        #pragma unroll
        for(int n=0;n<4;n++){
          float4 u=rb[((s*4+mt)*4+n)*32+lane];
          accA[n][0]+=u.x; accA[n][1]+=u.y; accA[n][2]+=u.z; accA[n][3]+=u.w;
        }
      // gates: nt order = f,i,o,cand; e: 0=(r0,c0) 1=(r0,c1) 2=(r1,c0) 3=(r1,c1)
      float gv[4][4];
      #pragma unroll
      for(int n=0;n<4;n++){
        gv[n][0]=accA[n][0]+xr[n].x;   gv[n][1]=accA[n][1]+xr[n].y;
        gv[n][2]=accA[n][2]+xr[4+n].x; gv[n][3]=accA[n][3]+xr[4+n].y;
      }
      #pragma unroll
      for(int e=0;e<4;e++){
        float f=sigf(gv[0][e]), ii=sigf(gv[1][e]);
        float o=sigf(gv[2][e]), cd=tanhf(gv[3][e]);
        cst[e]=f*cst[e]+ii*cd;
        hv[e]=o*tanhf(cst[e]);
      }
      // fragment store FIRST (cross-CTA dependency), then arrive
      unsigned msk=0xffffffffu;
      int sl0=(lane&~3)|(tg>>1), sl1=sl0+2;
      float u00=__shfl_sync(msk,hv[0],sl0), u01=__shfl_sync(msk,hv[1],sl0);
      float u20=__shfl_sync(msk,hv[2],sl0), u21=__shfl_sync(msk,hv[3],sl0);
      float v00=__shfl_sync(msk,hv[0],sl1), v01=__shfl_sync(msk,hv[1],sl1);
      float v20=__shfl_sync(msk,hv[2],sl1), v21=__shfl_sync(msk,hv[3],sl1);
      int odd=tg&1;
      float4 fr = make_float4(tf32f(odd?u01:u00), tf32f(odd?u21:u20),
                              tf32f(odd?v01:v00), tf32f(odd?v21:v20));
      ((float4*)(g_hfrag + (size_t)t*NB*NH))[cta*128 + mt*32 + lane] = fr;
      __syncwarp();                       // intra-warp ordering of frag STGs
      if(lane==0){                        // cumulative release arrival (+1)
        unsigned* fp = myArr + t;
        asm volatile("red.release.gpu.global.add.u32 [%0], %1;"
                     :: "l"(fp), "r"(1u) : "memory");
      }
      // h_seq output store, off the release path
      float* hw = out + ((size_t)t*NB + 16*mt + g)*NH + 8*cta + 2*tg;
      *(float2*)hw                = make_float2(hv[0],hv[1]);
      *(float2*)(hw+(size_t)8*NH) = make_float2(hv[2],hv[3]);
    }
  }

  if(kh==0){  // tails: h_final (== h_seq[511]) then c_final
    float* ho = out + HSEQ + (size_t)(16*mt+g)*NH + 8*cta + 2*tg;
    float* co = ho + (size_t)NB*NH;
    *(float2*)ho                = make_float2(hv[0],hv[1]);
    *(float2*)(ho+(size_t)8*NH) = make_float2(hv[2],hv[3]);
    *(float2*)co                = make_float2(cst[0],cst[1]);
    *(float2*)(co+(size_t)8*NH) = make_float2(cst[2],cst[3]);
  }
}

extern "C" void kernel_launch(void* const* d_in, const int* in_sizes, int n_in,
                              void* d_out, int out_size){
  const float* x =(const float*)d_in[0];
  const float* W1=(const float*)d_in[1];  const float* b1=(const float*)d_in[2];
  const float* W2=(const float*)d_in[3];  const float* b2=(const float*)d_in[4];
  const float* W3=(const float*)d_in[5];  const float* b3=(const float*)d_in[6];
  const float* W4=(const float*)d_in[7];  const float* b4=(const float*)d_in[8];
  const float* W5=(const float*)d_in[9];  const float* b5=(const float*)d_in[10];
  const float* W6=(const float*)d_in[11]; const float* b6=(const float*)d_in[12];
  const float* W7=(const float*)d_in[13]; const float* b7=(const float*)d_in[14];
  const float* W8=(const float*)d_in[15]; const float* b8=(const float*)d_in[16];
  float* out=(float*)d_out;

  cudaFuncSetAttribute(lstm_rec, cudaFuncAttributeMaxDynamicSharedMemorySize, 180224);

  dim3 grid(64,256);
  xg_gemm<<<grid,256>>>(x, W1,W3,W5,W7, b1,b3,b5,b7, b2,b4,b6,b8);
  lstm_rec<<<128,512,180224>>>(W2,W4,W6,W8, out);
}

// round 12
// speedup vs baseline: 1.4389x; 1.4389x over previous
#include <cuda_runtime.h>
#include <cuda_fp16.h>
#include <cstdint>

#define SQ 512
#define NB 64
#define NH 1024
#define NI 256
#define NG 4096
#define HSEQ ((size_t)SQ*NB*NH)

// scratch (no allocations allowed)
__device__ float    g_xg[(size_t)SQ*NB*NG];   // xg = x@Wx + bx + bh (fp32)
__device__ uint4    g_hfrag[(size_t)SQ*8192]; // h in fp16 A-fragment order, 64MB
__device__ unsigned g_flags[8*SQ];            // per-(group,step) arrival counters

__device__ __forceinline__ unsigned tf32u(float x){
  unsigned u; asm("cvt.rna.tf32.f32 %0, %1;" : "=r"(u) : "f"(x)); return u;
}
__device__ __forceinline__ float tf32f(float x){ return __uint_as_float(tf32u(x)); }
__device__ __forceinline__ void mma8(float d[4], unsigned a0,unsigned a1,unsigned a2,unsigned a3,
                                     unsigned b0,unsigned b1){
  asm("mma.sync.aligned.m16n8k8.row.col.f32.tf32.tf32.f32 "
      "{%0,%1,%2,%3},{%4,%5,%6,%7},{%8,%9},{%0,%1,%2,%3};"
      : "+f"(d[0]),"+f"(d[1]),"+f"(d[2]),"+f"(d[3])
      : "r"(a0),"r"(a1),"r"(a2),"r"(a3),"r"(b0),"r"(b1));
}
__device__ __forceinline__ void mma16(float d[4], unsigned a0,unsigned a1,unsigned a2,unsigned a3,
                                      unsigned b0,unsigned b1){
  asm("mma.sync.aligned.m16n8k16.row.col.f32.f16.f16.f32 "
      "{%0,%1,%2,%3},{%4,%5,%6,%7},{%8,%9},{%0,%1,%2,%3};"
      : "+f"(d[0]),"+f"(d[1]),"+f"(d[2]),"+f"(d[3])
      : "r"(a0),"r"(a1),"r"(a2),"r"(a3),"r"(b0),"r"(b1));
}
__device__ __forceinline__ unsigned packh2(float lo, float hi){
  __half2 h = __floats2half2_rn(lo, hi);
  return *reinterpret_cast<unsigned*>(&h);
}
__device__ __forceinline__ float sigf(float x){ return 1.f/(1.f+__expf(-x)); }

// ---------------------------------------------------------------------------
// Phase 1: xg[m][gate*1024+j] = x[m,:] @ Wgate[:, j] + bx + bh  (tf32 MMA)
// CTA tile 128(M) x 64(N), K=256 in 8 chunks of 32. 8 warps = 4(m) x 2(n).
// Block (0,0) also re-zeroes the recurrence sync flags.
// ---------------------------------------------------------------------------
__global__ void __launch_bounds__(256) xg_gemm(
    const float* __restrict__ x,
    const float* __restrict__ Wa,const float* __restrict__ Wb,
    const float* __restrict__ Wc,const float* __restrict__ Wd,
    const float* __restrict__ xa,const float* __restrict__ xb,
    const float* __restrict__ xc,const float* __restrict__ xd,
    const float* __restrict__ ha,const float* __restrict__ hb,
    const float* __restrict__ hc,const float* __restrict__ hd)
{
  __shared__ float As[128*36];
  __shared__ float Bs[32*72];
  __shared__ float bias[64];
  const int tid=threadIdx.x, w=tid>>5, lane=tid&31;
  const int g=lane>>2, tg=lane&3, wm=w>>1, wn=w&1;
  const int mbase=blockIdx.y*128, nb=blockIdx.x*64;
  const int gate=nb>>10, colbase=nb&1023;

  if (blockIdx.x==0 && blockIdx.y==0){           // flag reset for lstm_rec
    #pragma unroll
    for(int p=0;p<16;p++) g_flags[tid+p*256]=0u;
  }

  const float* Wg = gate==0?Wa:gate==1?Wb:gate==2?Wc:Wd;
  const float* bx = gate==0?xa:gate==1?xb:gate==2?xc:xd;
  const float* bh = gate==0?ha:gate==1?hb:gate==2?hc:hd;
  if (tid<64) bias[tid]=bx[colbase+tid]+bh[colbase+tid];

  float acc[2][4][4];
  #pragma unroll
  for(int i=0;i<2;i++)
    #pragma unroll
    for(int j=0;j<4;j++)
      #pragma unroll
      for(int e=0;e<4;e++) acc[i][j][e]=0.f;

  for(int kc=0;kc<8;kc++){
    #pragma unroll
    for(int p=0;p<4;p++){
      int fid=tid+p*256, row=fid>>3, c4=(fid&7)*4;
      float4 v=*(const float4*)(x+(size_t)(mbase+row)*NI+kc*32+c4);
      v.x=tf32f(v.x); v.y=tf32f(v.y); v.z=tf32f(v.z); v.w=tf32f(v.w);
      *(float4*)(As+row*36+c4)=v;
    }
    #pragma unroll
    for(int p=0;p<2;p++){
      int fid=tid+p*256, r=fid>>4, c4=(fid&15)*4;
      float4 v=*(const float4*)(Wg+(size_t)(kc*32+r)*NH+colbase+c4);
      v.x=tf32f(v.x); v.y=tf32f(v.y); v.z=tf32f(v.z); v.w=tf32f(v.w);
      *(float4*)(Bs+r*72+c4)=v;
    }
    __syncthreads();
    #pragma unroll
    for(int kk=0;kk<4;kk++){
      unsigned a[2][4];
      #pragma unroll
      for(int mt=0;mt<2;mt++){
        int ar=wm*32+mt*16+g, k0=kk*8+tg;
        a[mt][0]=__float_as_uint(As[ar*36+k0]);
        a[mt][1]=__float_as_uint(As[(ar+8)*36+k0]);
        a[mt][2]=__float_as_uint(As[ar*36+k0+4]);
        a[mt][3]=__float_as_uint(As[(ar+8)*36+k0+4]);
      }
      #pragma unroll
      for(int nt=0;nt<4;nt++){
        int nc=wn*32+nt*8+g, k0=kk*8+tg;
        unsigned b0=__float_as_uint(Bs[k0*72+nc]);
        unsigned b1=__float_as_uint(Bs[(k0+4)*72+nc]);
        mma8(acc[0][nt],a[0][0],a[0][1],a[0][2],a[0][3],b0,b1);
        mma8(acc[1][nt],a[1][0],a[1][1],a[1][2],a[1][3],b0,b1);
      }
    }
    __syncthreads();
  }
  #pragma unroll
  for(int mt=0;mt<2;mt++){
    #pragma unroll
    for(int nt=0;nt<4;nt++){
      int row0=mbase+wm*32+mt*16+g;
      int colL=wn*32+nt*8+2*tg;
      float b0v=bias[colL], b1v=bias[colL+1];
      float* o0=g_xg+(size_t)row0*NG+nb+colL;
      *(float2*)o0               = make_float2(acc[mt][nt][0]+b0v, acc[mt][nt][1]+b1v);
      *(float2*)(o0+(size_t)8*NG)= make_float2(acc[mt][nt][2]+b0v, acc[mt][nt][3]+b1v);
    }
  }
}

// ---------------------------------------------------------------------------
// Phase 2: persistent recurrence in fp16 MMA (m16n8k16), fp32 accum/state.
// 128 CTAs (1/SM), 256 threads (8 warps). CTA c owns h-cols [8c,8c+8) and the
// matching 8 cols of all 4 gates. Chunk16 j = h-cols [16j,16j+16) = CTAs 2j,2j+1.
//  - h exchanged via g_hfrag (fp16 A-fragments): uint4[t][j(64)][mt(4)][lane]
//    = {a0,a1,a2,a3}; halves written by CTA 2j (a0,a1) and 2j+1 (a2,a3) as
//    uint2 -- the producer's (2tg,2tg+1) column pairs pack directly, NO
//    shuffle transpose. Consumers __ldcg straight into MMA A operands.
//  - warp w (=kh slab, 8 slabs) computes the FULL 64x32 tile over chunk16s
//    j in [8w,8w+8): per j: 4 LDG.128 (A, all mt) + 2 LDS.128 (B, all gates)
//    + 16 MMA. B (Wh fp16, packed in smem Bp 64KB) read exactly once.
//  - 8-way kh reduction via red (2x64KB, t-parity); epilogue on warps 0-3
//    (same (g,tg)->rows/cols map as before); ONE __syncthreads per step.
//  - sync: 8 producer groups (CTAs 16G..16G+16) own flag g_flags[G*SQ+t];
//    4 epilogue warps/CTA arrive with red.release.gpu.add -> target 64.
//    Consumer warp w acquire-polls group w. Poll uses (<64): stale-safe.
// ---------------------------------------------------------------------------
__global__ void __launch_bounds__(256,1) lstm_rec(
    const float* __restrict__ Wh1,const float* __restrict__ Wh2,
    const float* __restrict__ Wh3,const float* __restrict__ Wh4,
    float* __restrict__ out)
{
  extern __shared__ float sm[];
  uint4*  Bp4  = (uint4*)sm;              // 4096 uint4 (64KB): packed fp16 B frags
  float4* red4 = (float4*)(sm + 16384);   // 2 x 4096 float4 (128KB): kh partials

  const int tid=threadIdx.x, w=tid>>5, lane=tid&31;
  const int g=lane>>2, tg=lane&3, cta=blockIdx.x;

  { // one-time fp16 B pack: Bp4[(j*2+p)*32+lane] = {b0,b1 of gate 2p, b0,b1 of 2p+1}
    const float* Whs[4]={Wh1,Wh2,Wh3,Wh4};
    for(int idx=tid; idx<4096; idx+=256){
      int ln=idx&31, p=(idx>>5)&1, j=idx>>6;
      int g_=ln>>2, tg_=ln&3;
      int col=8*cta+g_;
      int k0=16*j+2*tg_;
      uint4 val;
      const float* W0=Whs[2*p];
      const float* W1=Whs[2*p+1];
      val.x=packh2(W0[(size_t)k0*NH+col],     W0[(size_t)(k0+1)*NH+col]);
      val.y=packh2(W0[(size_t)(k0+8)*NH+col], W0[(size_t)(k0+9)*NH+col]);
      val.z=packh2(W1[(size_t)k0*NH+col],     W1[(size_t)(k0+1)*NH+col]);
      val.w=packh2(W1[(size_t)(k0+8)*NH+col], W1[(size_t)(k0+9)*NH+col]);
      Bp4[(j*2+p)*32+ln]=val;
    }
  }
  __syncthreads();

  unsigned* myArr = g_flags + (cta>>4)*SQ;   // producer arrival row (16-CTA group)
  unsigned* myPol = g_flags + w*SQ;          // consumer poll row (slab w)
  float cst[4]={0,0,0,0}, hv[4]={0,0,0,0};

  #pragma unroll 1
  for(int t=0;t<SQ;t++){
    // xg loads: independent of h -> issue before any waiting (epilogue warps)
    float2 xr[8];
    if(w<4){
      const float* xb = g_xg + ((size_t)t*NB + 16*w + g)*NG + 8*cta + 2*tg;
      #pragma unroll
      for(int nt=0;nt<4;nt++){
        xr[nt]   = __ldcg((const float2*)(xb + nt*NH));
        xr[4+nt] = __ldcg((const float2*)(xb + (size_t)8*NG + nt*NH));
      }
    }

    float acc[4][4][4];
    #pragma unroll
    for(int m=0;m<4;m++)
      #pragma unroll
      for(int n=0;n<4;n++)
        #pragma unroll
        for(int e=0;e<4;e++) acc[m][n][e]=0.f;

    if(t>0){
      { // per-warp acquire poll on this slab's producer group (converged)
        const unsigned* fp = myPol + (t-1);
        unsigned v;
        asm volatile("ld.acquire.gpu.global.u32 %0, [%1];" : "=r"(v) : "l"(fp) : "memory");
        while(v < 64u){
          __nanosleep(20);
          asm volatile("ld.acquire.gpu.global.u32 %0, [%1];" : "=r"(v) : "l"(fp) : "memory");
        }
      }
      const uint4* fb = g_hfrag + (size_t)(t-1)*8192;
      uint4 A[2][4], B0[2], B1[2];
      { int j=w*8;
        #pragma unroll
        for(int m=0;m<4;m++) A[0][m]=__ldcg(fb + ((j*4+m)*32+lane));
        B0[0]=Bp4[(j*2+0)*32+lane]; B1[0]=Bp4[(j*2+1)*32+lane];
      }
      #pragma unroll
      for(int jj=0;jj<8;jj++){
        int cur=jj&1, nxt=cur^1;
        if(jj<7){
          int j=w*8+jj+1;
          #pragma unroll
          for(int m=0;m<4;m++) A[nxt][m]=__ldcg(fb + ((j*4+m)*32+lane));
          B0[nxt]=Bp4[(j*2+0)*32+lane]; B1[nxt]=Bp4[(j*2+1)*32+lane];
        }
        #pragma unroll
        for(int m=0;m<4;m++){
          mma16(acc[m][0],A[cur][m].x,A[cur][m].y,A[cur][m].z,A[cur][m].w,B0[cur].x,B0[cur].y);
          mma16(acc[m][1],A[cur][m].x,A[cur][m].y,A[cur][m].z,A[cur][m].w,B0[cur].z,B0[cur].w);
          mma16(acc[m][2],A[cur][m].x,A[cur][m].y,A[cur][m].z,A[cur][m].w,B1[cur].x,B1[cur].y);
          mma16(acc[m][3],A[cur][m].x,A[cur][m].y,A[cur][m].z,A[cur][m].w,B1[cur].z,B1[cur].w);
        }
      }
    }

    float4* rb = red4 + (t&1)*4096;
    #pragma unroll
    for(int m=0;m<4;m++)                  // every warp writes its slab
      #pragma unroll
      for(int n=0;n<4;n++)
        rb[((w*16+m*4+n)*32+lane)] =
          make_float4(acc[m][n][0],acc[m][n][1],acc[m][n][2],acc[m][n][3]);
    __syncthreads();                      // the ONE barrier: red ready
    if(w<4){
      float ga[4][4];
      #pragma unroll
      for(int n=0;n<4;n++)
        #pragma unroll
        for(int e=0;e<4;e++) ga[n][e]=0.f;
      #pragma unroll
      for(int s=0;s<8;s++)
        #pragma unroll
        for(int n=0;n<4;n++){
          float4 u=rb[((s*16+w*4+n)*32+lane)];
          ga[n][0]+=u.x; ga[n][1]+=u.y; ga[n][2]+=u.z; ga[n][3]+=u.w;
        }
      // gates: nt order = f,i,o,cand; e: 0=(r0,c0) 1=(r0,c1) 2=(r1,c0) 3=(r1,c1)
      float gv[4][4];
      #pragma unroll
      for(int n=0;n<4;n++){
        gv[n][0]=ga[n][0]+xr[n].x;   gv[n][1]=ga[n][1]+xr[n].y;
        gv[n][2]=ga[n][2]+xr[4+n].x; gv[n][3]=ga[n][3]+xr[4+n].y;
      }
      #pragma unroll
      for(int e=0;e<4;e++){
        float f=sigf(gv[0][e]), ii=sigf(gv[1][e]);
        float o=sigf(gv[2][e]), cd=tanhf(gv[3][e]);
        cst[e]=f*cst[e]+ii*cd;
        hv[e]=o*tanhf(cst[e]);
      }
      // fragment store FIRST (cross-CTA dependency), then arrive
      unsigned p0=packh2(hv[0],hv[1]), p1=packh2(hv[2],hv[3]);
      uint2* fw = ((uint2*)(g_hfrag + (size_t)t*8192))
                  + (((cta>>1)*4 + w)*32 + lane)*2 + (cta&1);
      *fw = make_uint2(p0,p1);
      __syncwarp();                       // intra-warp ordering of frag STGs
      if(lane==0){                        // cumulative release arrival (+1)
        unsigned* fp = myArr + t;
        asm volatile("red.release.gpu.global.add.u32 [%0], %1;"
                     :: "l"(fp), "r"(1u) : "memory");
      }
      // h_seq output store (fp32), off the release path
      float* hw = out + ((size_t)t*NB + 16*w + g)*NH + 8*cta + 2*tg;
      *(float2*)hw                = make_float2(hv[0],hv[1]);
      *(float2*)(hw+(size_t)8*NH) = make_float2(hv[2],hv[3]);
    }
  }

  if(w<4){  // tails: h_final (== h_seq[511]) then c_final
    float* ho = out + HSEQ + (size_t)(16*w+g)*NH + 8*cta + 2*tg;
    float* co = ho + (size_t)NB*NH;
    *(float2*)ho                = make_float2(hv[0],hv[1]);
    *(float2*)(ho+(size_t)8*NH) = make_float2(hv[2],hv[3]);
    *(float2*)co                = make_float2(cst[0],cst[1]);
    *(float2*)(co+(size_t)8*NH) = make_float2(cst[2],cst[3]);
  }
}

extern "C" void kernel_launch(void* const* d_in, const int* in_sizes, int n_in,
                              void* d_out, int out_size){
  const float* x =(const float*)d_in[0];
  const float* W1=(const float*)d_in[1];  const float* b1=(const float*)d_in[2];
  const float* W2=(const float*)d_in[3];  const float* b2=(const float*)d_in[4];
  const float* W3=(const float*)d_in[5];  const float* b3=(const float*)d_in[6];
  const float* W4=(const float*)d_in[7];  const float* b4=(const float*)d_in[8];
  const float* W5=(const float*)d_in[9];  const float* b5=(const float*)d_in[10];
  const float* W6=(const float*)d_in[11]; const float* b6=(const float*)d_in[12];
  const float* W7=(const float*)d_in[13]; const float* b7=(const float*)d_in[14];
  const float* W8=(const float*)d_in[15]; const float* b8=(const float*)d_in[16];
  float* out=(float*)d_out;

  cudaFuncSetAttribute(lstm_rec, cudaFuncAttributeMaxDynamicSharedMemorySize, 196608);

  dim3 grid(64,256);
  xg_gemm<<<grid,256>>>(x, W1,W3,W5,W7, b1,b3,b5,b7, b2,b4,b6,b8);
  lstm_rec<<<128,256,196608>>>(W2,W4,W6,W8, out);
}